// round 4
// baseline (speedup 1.0000x reference)
#include <cuda_runtime.h>
#include <cuda_fp16.h>
#include <math.h>

#define GRES 128
#define NPIX 16384
#define TA1  4      // a1 tile per block
#define TA2  8      // a2 tile per block
#define SCB  4      // sc channels per smem stage

// Fused trilinear table: T[a2][a1][a0] -> 8 halves (6 used + pad). 33.5 MB.
__device__ uint4 g_T[GRES * GRES * GRES];

// ---------------------------------------------------------------------------
// Voxelize: T[a2][a1][a0][s] = sum_p sum_c plane_p * line_p  (604M FMA GEMM-ish)
//   p=0: plane0[sc][a1][a0] * line0[sc][a2]
//   p=1: plane1[sc][a2][a0] * line1[sc][a1]
//   p=2: plane2[sc][a2][a1] * line2[sc][a0]
// Block: 256 thr = 32 a0-groups(x4) x 8 (a1g x a2g). Thread: 4 a0 x 2 a1 x 2 a2
// voxels, 6 s accumulators each (96 regs). Warp lanes span all 128 a0 ->
// conflict-free LDS.128; scalar LDS are warp-uniform broadcasts.
// ---------------------------------------------------------------------------
__global__ __launch_bounds__(256)
void voxelize(const float* __restrict__ planes, const float* __restrict__ lines) {
    __shared__ float s_p0[SCB][TA1][GRES];
    __shared__ float s_p1[SCB][TA2][GRES];
    __shared__ float s_l2[SCB][GRES];
    __shared__ float s_l0[SCB][TA2];
    __shared__ float s_l1[SCB][TA1];
    __shared__ float s_p2[SCB][TA2][TA1];

    const int tid  = threadIdx.x;
    const int lane = tid & 31;
    const int wz   = tid >> 5;        // 0..7
    const int a1g  = wz >> 2;         // 0..1  -> a1 local = a1g*2 + {0,1}
    const int a2g  = wz & 3;          // 0..3  -> a2 local = a2g*2 + {0,1}
    const int a1b  = blockIdx.x * TA1;
    const int a2b  = blockIdx.y * TA2;
    const int a0   = lane * 4;

    float acc[6][2][2][4];
    #pragma unroll
    for (int c = 0; c < 6; c++)
        #pragma unroll
        for (int i = 0; i < 2; i++)
            #pragma unroll
            for (int j = 0; j < 2; j++)
                #pragma unroll
                for (int k = 0; k < 4; k++) acc[c][i][j][k] = 0.0f;

    #pragma unroll
    for (int ch = 0; ch < 6; ch++) {
        for (int cb = 0; cb < 16; cb += SCB) {
            const int scb = ch * 16 + cb;
            __syncthreads();
            // ---- cooperative smem stage (all coalesced) ----
            for (int i = tid; i < SCB * TA1 * GRES; i += 256) {
                int c0 = i & 127; int t = i >> 7; int r = t % TA1; int s = t / TA1;
                s_p0[s][r][c0] = planes[(size_t)(scb + s) * NPIX + (a1b + r) * GRES + c0];
            }
            for (int i = tid; i < SCB * TA2 * GRES; i += 256) {
                int c0 = i & 127; int t = i >> 7; int r = t % TA2; int s = t / TA2;
                s_p1[s][r][c0] = planes[(size_t)(96 + scb + s) * NPIX + (a2b + r) * GRES + c0];
            }
            for (int i = tid; i < SCB * GRES; i += 256) {
                int c0 = i & 127; int s = i >> 7;
                s_l2[s][c0] = lines[(size_t)(192 + scb + s) * GRES + c0];
            }
            if (tid < SCB * TA2) {
                int r = tid % TA2, s = tid / TA2;
                s_l0[s][r] = lines[(size_t)(scb + s) * GRES + a2b + r];
            } else if (tid < SCB * TA2 + SCB * TA1) {
                int u = tid - SCB * TA2; int r = u % TA1, s = u / TA1;
                s_l1[s][r] = lines[(size_t)(96 + scb + s) * GRES + a1b + r];
            }
            if (tid < SCB * TA2 * TA1) {
                int r1 = tid % TA1; int t = tid / TA1; int r2 = t % TA2; int s = t / TA2;
                s_p2[s][r2][r1] = planes[(size_t)(192 + scb + s) * NPIX +
                                         (a2b + r2) * GRES + (a1b + r1)];
            }
            __syncthreads();

            // ---- compute: 4 sc x 16 voxels x 3 fma ----
            #pragma unroll
            for (int s = 0; s < SCB; s++) {
                const float4 l2v = *(const float4*)&s_l2[s][a0];
                float4 p0v[2], p1v[2];
                float  L1v[2], L0v[2];
                #pragma unroll
                for (int d1 = 0; d1 < 2; d1++) {
                    int a1l = a1g * 2 + d1;
                    p0v[d1] = *(const float4*)&s_p0[s][a1l][a0];
                    L1v[d1] = s_l1[s][a1l];
                }
                #pragma unroll
                for (int d2 = 0; d2 < 2; d2++) {
                    int a2l = a2g * 2 + d2;
                    p1v[d2] = *(const float4*)&s_p1[s][a2l][a0];
                    L0v[d2] = s_l0[s][a2l];
                }
                #pragma unroll
                for (int d1 = 0; d1 < 2; d1++) {
                    #pragma unroll
                    for (int d2 = 0; d2 < 2; d2++) {
                        float P2v = s_p2[s][a2g * 2 + d2][a1g * 2 + d1];
                        acc[ch][d1][d2][0] += p0v[d1].x * L0v[d2] + p1v[d2].x * L1v[d1] + P2v * l2v.x;
                        acc[ch][d1][d2][1] += p0v[d1].y * L0v[d2] + p1v[d2].y * L1v[d1] + P2v * l2v.y;
                        acc[ch][d1][d2][2] += p0v[d1].z * L0v[d2] + p1v[d2].z * L1v[d1] + P2v * l2v.z;
                        acc[ch][d1][d2][3] += p0v[d1].w * L0v[d2] + p1v[d2].w * L1v[d1] + P2v * l2v.w;
                    }
                }
            }
        }
    }

    // ---- pack fp16 and store (64 B contiguous per voxel column) ----
    #pragma unroll
    for (int d1 = 0; d1 < 2; d1++) {
        int a1 = a1b + a1g * 2 + d1;
        #pragma unroll
        for (int d2 = 0; d2 < 2; d2++) {
            int a2 = a2b + a2g * 2 + d2;
            #pragma unroll
            for (int k = 0; k < 4; k++) {
                __half2 h0 = __floats2half2_rn(acc[0][d1][d2][k], acc[1][d1][d2][k]);
                __half2 h1 = __floats2half2_rn(acc[2][d1][d2][k], acc[3][d1][d2][k]);
                __half2 h2 = __floats2half2_rn(acc[4][d1][d2][k], acc[5][d1][d2][k]);
                uint4 q;
                q.x = *reinterpret_cast<unsigned*>(&h0);
                q.y = *reinterpret_cast<unsigned*>(&h1);
                q.z = *reinterpret_cast<unsigned*>(&h2);
                q.w = 0u;
                g_T[((size_t)a2 * GRES + a1) * GRES + a0 + k] = q;
            }
        }
    }
}

// ---------------------------------------------------------------------------
// Sample + Rodrigues: one thread per point. 8 LDG.128 trilinear gathers of the
// fused table, 6-channel trilerp, SE(3) exp map. No smem, no shuffles.
// ---------------------------------------------------------------------------
__device__ __forceinline__ void unp6(uint4 q, float f[6]) {
    __half2 h0 = *reinterpret_cast<__half2*>(&q.x);
    __half2 h1 = *reinterpret_cast<__half2*>(&q.y);
    __half2 h2 = *reinterpret_cast<__half2*>(&q.z);
    float2 a = __half22float2(h0);
    float2 b = __half22float2(h1);
    float2 c = __half22float2(h2);
    f[0] = a.x; f[1] = a.y; f[2] = b.x; f[3] = b.y; f[4] = c.x; f[5] = c.y;
}

__global__ __launch_bounds__(256)
void sample_warp(const float* __restrict__ xyz, const float* __restrict__ vd,
                 const float* __restrict__ aabb, float* __restrict__ out,
                 int npts) {
    int pt = blockIdx.x * 256 + threadIdx.x;
    if (pt >= npts) return;

    const float X0 = xyz[pt * 3 + 0], X1 = xyz[pt * 3 + 1], X2 = xyz[pt * 3 + 2];
    const float Pc[3] = {X0, X1, X2};

    int ii[2][3];
    float w[3];
    #pragma unroll
    for (int d = 0; d < 3; d++) {
        float lo = __ldg(&aabb[d]), hi = __ldg(&aabb[3 + d]);
        float xn = (Pc[d] - lo) * (2.0f / (hi - lo)) - 1.0f;
        float f = fmaf(xn, 63.5f, 63.5f);
        f = fminf(fmaxf(f, 0.0f), 127.0f);
        float ff = floorf(f);
        ii[0][d] = (int)ff;
        ii[1][d] = min(ii[0][d] + 1, GRES - 1);
        w[d] = f - ff;
    }

    // gather 8 corners: f[c2][c1][c0][6]
    float f[2][2][2][6];
    #pragma unroll
    for (int c2 = 0; c2 < 2; c2++)
        #pragma unroll
        for (int c1 = 0; c1 < 2; c1++)
            #pragma unroll
            for (int c0 = 0; c0 < 2; c0++) {
                uint4 q = __ldg(&g_T[((size_t)ii[c2][2] * GRES + ii[c1][1]) * GRES
                                     + ii[c0][0]]);
                unp6(q, f[c2][c1][c0]);
            }

    // trilerp 6 channels
    float bw[6];
    #pragma unroll
    for (int j = 0; j < 6; j++) {
        float e00 = fmaf(w[0], f[0][0][1][j] - f[0][0][0][j], f[0][0][0][j]);
        float e01 = fmaf(w[0], f[0][1][1][j] - f[0][1][0][j], f[0][1][0][j]);
        float e10 = fmaf(w[0], f[1][0][1][j] - f[1][0][0][j], f[1][0][0][j]);
        float e11 = fmaf(w[0], f[1][1][1][j] - f[1][1][0][j], f[1][1][0][j]);
        float g0  = fmaf(w[1], e01 - e00, e00);
        float g1  = fmaf(w[1], e11 - e10, e10);
        bw[j] = fmaf(w[2], g1 - g0, g0);
    }

    // Rodrigues / SE(3) exp map
    float w0 = bw[0], w1 = bw[1], w2 = bw[2];
    float v0 = bw[3], v1 = bw[4], v2 = bw[5];

    float th2 = fmaf(w0, w0, fmaf(w1, w1, w2 * w2));
    th2 = fmaxf(th2, 1e-6f);
    float th  = sqrtf(th2);
    float inv = 1.0f / th;
    w0 *= inv; w1 *= inv; w2 *= inv;
    v0 *= inv; v1 *= inv; v2 *= inv;

    float q  = fmaf(w0, w0, fmaf(w1, w1, w2 * w2));
    float s  = sinf(th);
    float co = cosf(th);
    float cm = 1.0f - co;
    float ts = th - s;

    float rD = 1.0f - cm * q;
    float pD = th - ts * q;

    float D0 = vd[pt * 3 + 0], D1 = vd[pt * 3 + 1], D2 = vd[pt * 3 + 2];

    float wdV = fmaf(w0, v0, fmaf(w1, v1, w2 * v2));
    float t0 = pD * v0 + cm * (w1 * v2 - w2 * v1) + ts * w0 * wdV;
    float t1 = pD * v1 + cm * (w2 * v0 - w0 * v2) + ts * w1 * wdV;
    float t2 = pD * v2 + cm * (w0 * v1 - w1 * v0) + ts * w2 * wdV;

    float wdX = fmaf(w0, X0, fmaf(w1, X1, w2 * X2));
    float xw0 = rD * X0 + s * (w1 * X2 - w2 * X1) + cm * w0 * wdX + t0;
    float xw1 = rD * X1 + s * (w2 * X0 - w0 * X2) + cm * w1 * wdX + t1;
    float xw2 = rD * X2 + s * (w0 * X1 - w1 * X0) + cm * w2 * wdX + t2;

    float wdD = fmaf(w0, D0, fmaf(w1, D1, w2 * D2));
    float vw0 = rD * D0 + s * (w1 * D2 - w2 * D1) + cm * w0 * wdD;
    float vw1 = rD * D1 + s * (w2 * D0 - w0 * D2) + cm * w1 * wdD;
    float vw2 = rD * D2 + s * (w0 * D1 - w1 * D0) + cm * w2 * wdD;

    out[(size_t)pt * 3 + 0] = xw0;
    out[(size_t)pt * 3 + 1] = xw1;
    out[(size_t)pt * 3 + 2] = xw2;
    size_t off = (size_t)npts * 3;
    out[off + (size_t)pt * 3 + 0] = vw0;
    out[off + (size_t)pt * 3 + 1] = vw1;
    out[off + (size_t)pt * 3 + 2] = vw2;
}

// ---------------------------------------------------------------------------
// Launch: voxelize (fused 3D table) -> sample+warp. Graph-capturable.
// Inputs: xyz, viewdirs, transforms(unused), ray_valid(unused),
//         planes, lines, ray_aabb
// ---------------------------------------------------------------------------
extern "C" void kernel_launch(void* const* d_in, const int* in_sizes, int n_in,
                              void* d_out, int out_size) {
    const float* xyz    = (const float*)d_in[0];
    const float* vdirs  = (const float*)d_in[1];
    const float* planes = (const float*)d_in[4];
    const float* lines  = (const float*)d_in[5];
    const float* aabb   = (const float*)d_in[6];
    float* out = (float*)d_out;

    const int npts = in_sizes[0] / 3;

    voxelize<<<dim3(GRES / TA1, GRES / TA2), 256>>>(planes, lines);
    sample_warp<<<(npts + 255) / 256, 256>>>(xyz, vdirs, aabb, out, npts);
}

// round 5
// speedup vs baseline: 1.0688x; 1.0688x over previous
#include <cuda_runtime.h>
#include <cuda_fp16.h>
#include <math.h>

#define GRES 128
#define NPIX 16384
#define TA1  8      // a1 rows per block (one per warp)
#define TA2  2      // a2 rows per block (per thread)

// Fused trilinear table: T[a2][a1][a0] -> uint4 (6 halves + pad). 33.5 MB.
__device__ uint4 g_T[GRES * GRES * GRES];

// Packed f32x2 helpers (sm_103a)
#define FMA2(d, a, b, c) \
    asm("fma.rn.f32x2 %0, %1, %2, %3;" : "=l"(d) : "l"(a), "l"(b), "l"(c))
#define PACK2(out, lo, hi) \
    asm("mov.b64 %0, {%1, %2};" : "=l"(out) : "f"(lo), "f"(hi))
#define UNPACK2(lo, hi, in) \
    asm("mov.b64 {%0, %1}, %2;" : "=f"(lo), "=f"(hi) : "l"(in))

// ---------------------------------------------------------------------------
// Voxelize: T[a2][a1][a0][s] = sum_p sum_c plane_p * line_p   (604M MAC)
//   p=0: plane0[sc][a1][a0] * line0[sc][a2]
//   p=1: plane1[sc][a2][a0] * line1[sc][a1]
//   p=2: plane2[sc][a2][a1] * line2[sc][a0]
// Runtime loop over c (16 iters); stage holds the 6 slices {s*16+c} so the
// s-loop indexing acc[s] is a tiny static unroll -> accumulators provably in
// registers. Thread: 2 a2 x 4 a0 voxels x 6 s as 24 f32x2 accumulators.
// Block: 256 thr = 8 warps (one a1 each) x 32 lanes (4 a0 each).
// ---------------------------------------------------------------------------
__global__ __launch_bounds__(256, 2)
void voxelize(const float* __restrict__ planes, const float* __restrict__ lines) {
    __shared__ float s_p0[6][TA1][GRES];   // 24 KB
    __shared__ float s_p1[6][TA2][GRES];   // 6 KB
    __shared__ float s_l2[6][GRES];        // 3 KB
    __shared__ float s_l0[6][TA2];
    __shared__ float s_l1[6][TA1];
    __shared__ float s_p2[6][TA2][TA1];

    const int tid  = threadIdx.x;
    const int lane = tid & 31;
    const int a1l  = tid >> 5;             // warp id = local a1
    const int a1b  = blockIdx.x * TA1;
    const int a2b  = blockIdx.y * TA2;
    const int a0   = lane * 4;

    unsigned long long acc[6][TA2][2];     // [s][a2][a0 pair] packed f32x2
    #pragma unroll
    for (int s = 0; s < 6; s++)
        #pragma unroll
        for (int d = 0; d < TA2; d++) {
            acc[s][d][0] = 0ull; acc[s][d][1] = 0ull;
        }

    for (int c = 0; c < 16; c++) {         // runtime loop: no acc indexing
        __syncthreads();
        // ---- stage: 6 s-slices of channel c (all coalesced) ----
        for (int i = tid; i < 6 * TA1 * GRES; i += 256) {
            int x = i & 127; int t = i >> 7; int r = t & 7; int s = t >> 3;
            s_p0[s][r][x] = planes[(size_t)(s * 16 + c) * NPIX + (a1b + r) * GRES + x];
        }
        for (int i = tid; i < 6 * TA2 * GRES; i += 256) {
            int x = i & 127; int t = i >> 7; int r = t & 1; int s = t >> 1;
            s_p1[s][r][x] = planes[(size_t)(96 + s * 16 + c) * NPIX + (a2b + r) * GRES + x];
        }
        for (int i = tid; i < 6 * GRES; i += 256) {
            int x = i & 127; int s = i >> 7;
            s_l2[s][x] = lines[(size_t)(192 + s * 16 + c) * GRES + x];
        }
        if (tid < 12) {                                   // l0: 6x2
            int s = tid >> 1, r = tid & 1;
            s_l0[s][r] = lines[(size_t)(s * 16 + c) * GRES + a2b + r];
        }
        if (tid >= 32 && tid < 80) {                      // l1: 6x8
            int u = tid - 32; int s = u >> 3, r = u & 7;
            s_l1[s][r] = lines[(size_t)(96 + s * 16 + c) * GRES + a1b + r];
        }
        if (tid >= 96 && tid < 192) {                     // p2: 6x2x8
            int u = tid - 96; int r1 = u & 7; int r2 = (u >> 3) & 1; int s = u >> 4;
            s_p2[s][r2][r1] = planes[(size_t)(192 + s * 16 + c) * NPIX +
                                     (a2b + r2) * GRES + (a1b + r1)];
        }
        __syncthreads();

        // ---- accumulate: static s-unroll, packed fma ----
        #pragma unroll
        for (int s = 0; s < 6; s++) {
            const unsigned long long p0k0 = *(const unsigned long long*)&s_p0[s][a1l][a0];
            const unsigned long long p0k1 = *(const unsigned long long*)&s_p0[s][a1l][a0 + 2];
            const unsigned long long l2k0 = *(const unsigned long long*)&s_l2[s][a0];
            const unsigned long long l2k1 = *(const unsigned long long*)&s_l2[s][a0 + 2];
            const float l1s = s_l1[s][a1l];
            unsigned long long l1d; PACK2(l1d, l1s, l1s);

            #pragma unroll
            for (int d = 0; d < TA2; d++) {
                const unsigned long long p1k0 = *(const unsigned long long*)&s_p1[s][d][a0];
                const unsigned long long p1k1 = *(const unsigned long long*)&s_p1[s][d][a0 + 2];
                const float l0s = s_l0[s][d];
                const float p2s = s_p2[s][d][a1l];
                unsigned long long l0d, p2d;
                PACK2(l0d, l0s, l0s);
                PACK2(p2d, p2s, p2s);

                FMA2(acc[s][d][0], p0k0, l0d, acc[s][d][0]);
                FMA2(acc[s][d][1], p0k1, l0d, acc[s][d][1]);
                FMA2(acc[s][d][0], p1k0, l1d, acc[s][d][0]);
                FMA2(acc[s][d][1], p1k1, l1d, acc[s][d][1]);
                FMA2(acc[s][d][0], l2k0, p2d, acc[s][d][0]);
                FMA2(acc[s][d][1], l2k1, p2d, acc[s][d][1]);
            }
        }
    }

    // ---- epilogue: unpack, convert fp16, store (coalesced uint4) ----
    const int a1 = a1b + a1l;
    #pragma unroll
    for (int d = 0; d < TA2; d++) {
        const int a2 = a2b + d;
        float v[6][4];
        #pragma unroll
        for (int s = 0; s < 6; s++) {
            UNPACK2(v[s][0], v[s][1], acc[s][d][0]);
            UNPACK2(v[s][2], v[s][3], acc[s][d][1]);
        }
        uint4* dst = &g_T[((size_t)a2 * GRES + a1) * GRES + a0];
        #pragma unroll
        for (int j = 0; j < 4; j++) {
            __half2 h0 = __floats2half2_rn(v[0][j], v[1][j]);
            __half2 h1 = __floats2half2_rn(v[2][j], v[3][j]);
            __half2 h2 = __floats2half2_rn(v[4][j], v[5][j]);
            uint4 q;
            q.x = *reinterpret_cast<unsigned*>(&h0);
            q.y = *reinterpret_cast<unsigned*>(&h1);
            q.z = *reinterpret_cast<unsigned*>(&h2);
            q.w = 0u;
            dst[j] = q;
        }
    }
}

// ---------------------------------------------------------------------------
// Sample + Rodrigues: one thread per point; 8 LDG.128 trilinear gathers.
// ---------------------------------------------------------------------------
__device__ __forceinline__ void unp6(uint4 q, float f[6]) {
    __half2 h0 = *reinterpret_cast<__half2*>(&q.x);
    __half2 h1 = *reinterpret_cast<__half2*>(&q.y);
    __half2 h2 = *reinterpret_cast<__half2*>(&q.z);
    float2 a = __half22float2(h0);
    float2 b = __half22float2(h1);
    float2 c = __half22float2(h2);
    f[0] = a.x; f[1] = a.y; f[2] = b.x; f[3] = b.y; f[4] = c.x; f[5] = c.y;
}

__global__ __launch_bounds__(256)
void sample_warp(const float* __restrict__ xyz, const float* __restrict__ vd,
                 const float* __restrict__ aabb, float* __restrict__ out,
                 int npts) {
    int pt = blockIdx.x * 256 + threadIdx.x;
    if (pt >= npts) return;

    const float X0 = xyz[pt * 3 + 0], X1 = xyz[pt * 3 + 1], X2 = xyz[pt * 3 + 2];
    const float Pc[3] = {X0, X1, X2};

    int ii[2][3];
    float w[3];
    #pragma unroll
    for (int d = 0; d < 3; d++) {
        float lo = __ldg(&aabb[d]), hi = __ldg(&aabb[3 + d]);
        float xn = (Pc[d] - lo) * (2.0f / (hi - lo)) - 1.0f;
        float f = fmaf(xn, 63.5f, 63.5f);
        f = fminf(fmaxf(f, 0.0f), 127.0f);
        float ff = floorf(f);
        ii[0][d] = (int)ff;
        ii[1][d] = min(ii[0][d] + 1, GRES - 1);
        w[d] = f - ff;
    }

    float f[2][2][2][6];
    #pragma unroll
    for (int c2 = 0; c2 < 2; c2++)
        #pragma unroll
        for (int c1 = 0; c1 < 2; c1++)
            #pragma unroll
            for (int c0 = 0; c0 < 2; c0++) {
                uint4 q = __ldg(&g_T[((size_t)ii[c2][2] * GRES + ii[c1][1]) * GRES
                                     + ii[c0][0]]);
                unp6(q, f[c2][c1][c0]);
            }

    float bw[6];
    #pragma unroll
    for (int j = 0; j < 6; j++) {
        float e00 = fmaf(w[0], f[0][0][1][j] - f[0][0][0][j], f[0][0][0][j]);
        float e01 = fmaf(w[0], f[0][1][1][j] - f[0][1][0][j], f[0][1][0][j]);
        float e10 = fmaf(w[0], f[1][0][1][j] - f[1][0][0][j], f[1][0][0][j]);
        float e11 = fmaf(w[0], f[1][1][1][j] - f[1][1][0][j], f[1][1][0][j]);
        float g0  = fmaf(w[1], e01 - e00, e00);
        float g1  = fmaf(w[1], e11 - e10, e10);
        bw[j] = fmaf(w[2], g1 - g0, g0);
    }

    float w0 = bw[0], w1 = bw[1], w2 = bw[2];
    float v0 = bw[3], v1 = bw[4], v2 = bw[5];

    float th2 = fmaf(w0, w0, fmaf(w1, w1, w2 * w2));
    th2 = fmaxf(th2, 1e-6f);
    float th  = sqrtf(th2);
    float inv = 1.0f / th;
    w0 *= inv; w1 *= inv; w2 *= inv;
    v0 *= inv; v1 *= inv; v2 *= inv;

    float q  = fmaf(w0, w0, fmaf(w1, w1, w2 * w2));
    float s  = sinf(th);
    float co = cosf(th);
    float cm = 1.0f - co;
    float ts = th - s;

    float rD = 1.0f - cm * q;
    float pD = th - ts * q;

    float D0 = vd[pt * 3 + 0], D1 = vd[pt * 3 + 1], D2 = vd[pt * 3 + 2];

    float wdV = fmaf(w0, v0, fmaf(w1, v1, w2 * v2));
    float t0 = pD * v0 + cm * (w1 * v2 - w2 * v1) + ts * w0 * wdV;
    float t1 = pD * v1 + cm * (w2 * v0 - w0 * v2) + ts * w1 * wdV;
    float t2 = pD * v2 + cm * (w0 * v1 - w1 * v0) + ts * w2 * wdV;

    float wdX = fmaf(w0, X0, fmaf(w1, X1, w2 * X2));
    float xw0 = rD * X0 + s * (w1 * X2 - w2 * X1) + cm * w0 * wdX + t0;
    float xw1 = rD * X1 + s * (w2 * X0 - w0 * X2) + cm * w1 * wdX + t1;
    float xw2 = rD * X2 + s * (w0 * X1 - w1 * X0) + cm * w2 * wdX + t2;

    float wdD = fmaf(w0, D0, fmaf(w1, D1, w2 * D2));
    float vw0 = rD * D0 + s * (w1 * D2 - w2 * D1) + cm * w0 * wdD;
    float vw1 = rD * D1 + s * (w2 * D0 - w0 * D2) + cm * w1 * wdD;
    float vw2 = rD * D2 + s * (w0 * D1 - w1 * D0) + cm * w2 * wdD;

    out[(size_t)pt * 3 + 0] = xw0;
    out[(size_t)pt * 3 + 1] = xw1;
    out[(size_t)pt * 3 + 2] = xw2;
    size_t off = (size_t)npts * 3;
    out[off + (size_t)pt * 3 + 0] = vw0;
    out[off + (size_t)pt * 3 + 1] = vw1;
    out[off + (size_t)pt * 3 + 2] = vw2;
}

// ---------------------------------------------------------------------------
extern "C" void kernel_launch(void* const* d_in, const int* in_sizes, int n_in,
                              void* d_out, int out_size) {
    const float* xyz    = (const float*)d_in[0];
    const float* vdirs  = (const float*)d_in[1];
    const float* planes = (const float*)d_in[4];
    const float* lines  = (const float*)d_in[5];
    const float* aabb   = (const float*)d_in[6];
    float* out = (float*)d_out;

    const int npts = in_sizes[0] / 3;

    voxelize<<<dim3(GRES / TA1, GRES / TA2), 256>>>(planes, lines);
    sample_warp<<<(npts + 255) / 256, 256>>>(xyz, vdirs, aabb, out, npts);
}

// round 6
// speedup vs baseline: 2.2850x; 2.1378x over previous
#include <cuda_runtime.h>
#include <cuda_fp16.h>
#include <math.h>

#define GRES 128
#define NPIX 16384

// Fused trilinear table: T[a2][a1][a0] -> uint4 (6 halves + pad). 33.5 MB.
__device__ uint4 g_T[GRES * GRES * GRES];

// Packed f32x2 helpers (sm_103a)
#define FMA2(d, a, b, c) \
    asm("fma.rn.f32x2 %0, %1, %2, %3;" : "=l"(d) : "l"(a), "l"(b), "l"(c))
#define PACK2(out, lo, hi) \
    asm("mov.b64 %0, {%1, %2};" : "=l"(out) : "f"(lo), "f"(hi))
#define UNPACK2(lo, hi, in) \
    asm("mov.b64 {%0, %1}, %2;" : "=f"(lo), "=f"(hi) : "l"(in))

// ---------------------------------------------------------------------------
// Voxelize, register-direct: T[a2][a1][a0][s] = sum_c of
//   plane0[sc][a1][a0]*line0[sc][a2] + plane1[sc][a2][a0]*line1[sc][a1]
// + plane2[sc][a2][a1]*line2[sc][a0]
// Block = 128 thr = 4 warps (one a1 each), all sharing a 4-wide a2 quad.
// Thread: 4 a0 (lane*4) x 4 a2 x 6 s = 48 f32x2 accumulators (static idx).
// Big operands stream from gmem as coalesced LDG.128 (L1/L2 cached);
// tiny scalar tables staged in smem ONCE; no barriers in the c-loop.
// ---------------------------------------------------------------------------
__global__ __launch_bounds__(128)
void voxelize(const float* __restrict__ planes, const float* __restrict__ lines) {
    __shared__ float s_l0[96][4];        // line0[sc][a2 quad]
    __shared__ float s_l1[96][4];        // line1[sc][a1 quad]
    __shared__ float s_p2[96][4][4];     // plane2[sc][a1 local][a2 quad]

    const int tid  = threadIdx.x;
    const int lane = tid & 31;
    const int wid  = tid >> 5;           // local a1
    const int a1b  = blockIdx.x * 4;
    const int a2b  = blockIdx.y * 4;
    const int a1   = a1b + wid;
    const int a0   = lane * 4;

    // ---- one-time staging of scalar tables (9 KB) ----
    for (int i = tid; i < 384; i += 128) {
        int sc = i >> 2, d = i & 3;
        s_l0[sc][d] = lines[(size_t)sc * GRES + a2b + d];
    }
    for (int i = tid; i < 384; i += 128) {
        int sc = i >> 2, r = i & 3;
        s_l1[sc][r] = lines[(size_t)(96 + sc) * GRES + a1b + r];
    }
    for (int i = tid; i < 1536; i += 128) {
        int sc = i >> 4, r = (i >> 2) & 3, d = i & 3;
        s_p2[sc][r][d] = planes[(size_t)(192 + sc) * NPIX + (a2b + d) * GRES + (a1b + r)];
    }
    __syncthreads();

    unsigned long long acc[6][4][2];
    #pragma unroll
    for (int s = 0; s < 6; s++)
        #pragma unroll
        for (int d = 0; d < 4; d++) {
            acc[s][d][0] = 0ull; acc[s][d][1] = 0ull;
        }

    const float* __restrict__ p0base = planes;
    const float* __restrict__ p1base = planes + (size_t)96 * NPIX;
    const float* __restrict__ l2base = lines + (size_t)192 * GRES;

    for (int c = 0; c < 16; c++) {
        #pragma unroll
        for (int s = 0; s < 6; s++) {
            const int sc = s * 16 + c;
            ulonglong2 P0 = __ldg((const ulonglong2*)(p0base + (size_t)sc * NPIX + a1 * GRES + a0));
            ulonglong2 L2 = __ldg((const ulonglong2*)(l2base + (size_t)sc * GRES + a0));
            float4 l0q = *(const float4*)&s_l0[sc][0];           // warp-uniform
            float4 p2q = *(const float4*)&s_p2[sc][wid][0];      // warp-uniform
            float  l1s = s_l1[sc][wid];                          // warp-uniform
            unsigned long long l1d; PACK2(l1d, l1s, l1s);
            const float l0a[4] = {l0q.x, l0q.y, l0q.z, l0q.w};
            const float p2a[4] = {p2q.x, p2q.y, p2q.z, p2q.w};

            #pragma unroll
            for (int d = 0; d < 4; d++) {
                ulonglong2 P1 = __ldg((const ulonglong2*)(p1base + (size_t)sc * NPIX + (a2b + d) * GRES + a0));
                unsigned long long l0d, p2d;
                PACK2(l0d, l0a[d], l0a[d]);
                PACK2(p2d, p2a[d], p2a[d]);
                FMA2(acc[s][d][0], P0.x, l0d, acc[s][d][0]);
                FMA2(acc[s][d][1], P0.y, l0d, acc[s][d][1]);
                FMA2(acc[s][d][0], P1.x, l1d, acc[s][d][0]);
                FMA2(acc[s][d][1], P1.y, l1d, acc[s][d][1]);
                FMA2(acc[s][d][0], L2.x, p2d, acc[s][d][0]);
                FMA2(acc[s][d][1], L2.y, p2d, acc[s][d][1]);
            }
        }
    }

    // ---- epilogue: unpack, fp16 pack, coalesced STG.128 ----
    #pragma unroll
    for (int d = 0; d < 4; d++) {
        float v[6][4];
        #pragma unroll
        for (int s = 0; s < 6; s++) {
            UNPACK2(v[s][0], v[s][1], acc[s][d][0]);
            UNPACK2(v[s][2], v[s][3], acc[s][d][1]);
        }
        uint4* dst = &g_T[(((size_t)(a2b + d)) * GRES + a1) * GRES + a0];
        #pragma unroll
        for (int j = 0; j < 4; j++) {
            __half2 h0 = __floats2half2_rn(v[0][j], v[1][j]);
            __half2 h1 = __floats2half2_rn(v[2][j], v[3][j]);
            __half2 h2 = __floats2half2_rn(v[4][j], v[5][j]);
            uint4 q;
            q.x = *reinterpret_cast<unsigned*>(&h0);
            q.y = *reinterpret_cast<unsigned*>(&h1);
            q.z = *reinterpret_cast<unsigned*>(&h2);
            q.w = 0u;
            dst[j] = q;
        }
    }
}

// ---------------------------------------------------------------------------
// Sample + Rodrigues: one thread per point; 8 LDG.128 trilinear gathers.
// ---------------------------------------------------------------------------
__device__ __forceinline__ void unp6(uint4 q, float f[6]) {
    __half2 h0 = *reinterpret_cast<__half2*>(&q.x);
    __half2 h1 = *reinterpret_cast<__half2*>(&q.y);
    __half2 h2 = *reinterpret_cast<__half2*>(&q.z);
    float2 a = __half22float2(h0);
    float2 b = __half22float2(h1);
    float2 c = __half22float2(h2);
    f[0] = a.x; f[1] = a.y; f[2] = b.x; f[3] = b.y; f[4] = c.x; f[5] = c.y;
}

__global__ __launch_bounds__(256)
void sample_warp(const float* __restrict__ xyz, const float* __restrict__ vd,
                 const float* __restrict__ aabb, float* __restrict__ out,
                 int npts) {
    int pt = blockIdx.x * 256 + threadIdx.x;
    if (pt >= npts) return;

    const float X0 = xyz[pt * 3 + 0], X1 = xyz[pt * 3 + 1], X2 = xyz[pt * 3 + 2];
    const float Pc[3] = {X0, X1, X2};

    int ii[2][3];
    float w[3];
    #pragma unroll
    for (int d = 0; d < 3; d++) {
        float lo = __ldg(&aabb[d]), hi = __ldg(&aabb[3 + d]);
        float xn = (Pc[d] - lo) * (2.0f / (hi - lo)) - 1.0f;
        float f = fmaf(xn, 63.5f, 63.5f);
        f = fminf(fmaxf(f, 0.0f), 127.0f);
        float ff = floorf(f);
        ii[0][d] = (int)ff;
        ii[1][d] = min(ii[0][d] + 1, GRES - 1);
        w[d] = f - ff;
    }

    float f[2][2][2][6];
    #pragma unroll
    for (int c2 = 0; c2 < 2; c2++)
        #pragma unroll
        for (int c1 = 0; c1 < 2; c1++)
            #pragma unroll
            for (int c0 = 0; c0 < 2; c0++) {
                uint4 q = __ldg(&g_T[((size_t)ii[c2][2] * GRES + ii[c1][1]) * GRES
                                     + ii[c0][0]]);
                unp6(q, f[c2][c1][c0]);
            }

    float bw[6];
    #pragma unroll
    for (int j = 0; j < 6; j++) {
        float e00 = fmaf(w[0], f[0][0][1][j] - f[0][0][0][j], f[0][0][0][j]);
        float e01 = fmaf(w[0], f[0][1][1][j] - f[0][1][0][j], f[0][1][0][j]);
        float e10 = fmaf(w[0], f[1][0][1][j] - f[1][0][0][j], f[1][0][0][j]);
        float e11 = fmaf(w[0], f[1][1][1][j] - f[1][1][0][j], f[1][1][0][j]);
        float g0  = fmaf(w[1], e01 - e00, e00);
        float g1  = fmaf(w[1], e11 - e10, e10);
        bw[j] = fmaf(w[2], g1 - g0, g0);
    }

    float w0 = bw[0], w1 = bw[1], w2 = bw[2];
    float v0 = bw[3], v1 = bw[4], v2 = bw[5];

    float th2 = fmaf(w0, w0, fmaf(w1, w1, w2 * w2));
    th2 = fmaxf(th2, 1e-6f);
    float th  = sqrtf(th2);
    float inv = 1.0f / th;
    w0 *= inv; w1 *= inv; w2 *= inv;
    v0 *= inv; v1 *= inv; v2 *= inv;

    float q  = fmaf(w0, w0, fmaf(w1, w1, w2 * w2));
    float s  = sinf(th);
    float co = cosf(th);
    float cm = 1.0f - co;
    float ts = th - s;

    float rD = 1.0f - cm * q;
    float pD = th - ts * q;

    float D0 = vd[pt * 3 + 0], D1 = vd[pt * 3 + 1], D2 = vd[pt * 3 + 2];

    float wdV = fmaf(w0, v0, fmaf(w1, v1, w2 * v2));
    float t0 = pD * v0 + cm * (w1 * v2 - w2 * v1) + ts * w0 * wdV;
    float t1 = pD * v1 + cm * (w2 * v0 - w0 * v2) + ts * w1 * wdV;
    float t2 = pD * v2 + cm * (w0 * v1 - w1 * v0) + ts * w2 * wdV;

    float wdX = fmaf(w0, X0, fmaf(w1, X1, w2 * X2));
    float xw0 = rD * X0 + s * (w1 * X2 - w2 * X1) + cm * w0 * wdX + t0;
    float xw1 = rD * X1 + s * (w2 * X0 - w0 * X2) + cm * w1 * wdX + t1;
    float xw2 = rD * X2 + s * (w0 * X1 - w1 * X0) + cm * w2 * wdX + t2;

    float wdD = fmaf(w0, D0, fmaf(w1, D1, w2 * D2));
    float vw0 = rD * D0 + s * (w1 * D2 - w2 * D1) + cm * w0 * wdD;
    float vw1 = rD * D1 + s * (w2 * D0 - w0 * D2) + cm * w1 * wdD;
    float vw2 = rD * D2 + s * (w0 * D1 - w1 * D0) + cm * w2 * wdD;

    out[(size_t)pt * 3 + 0] = xw0;
    out[(size_t)pt * 3 + 1] = xw1;
    out[(size_t)pt * 3 + 2] = xw2;
    size_t off = (size_t)npts * 3;
    out[off + (size_t)pt * 3 + 0] = vw0;
    out[off + (size_t)pt * 3 + 1] = vw1;
    out[off + (size_t)pt * 3 + 2] = vw2;
}

// ---------------------------------------------------------------------------
extern "C" void kernel_launch(void* const* d_in, const int* in_sizes, int n_in,
                              void* d_out, int out_size) {
    const float* xyz    = (const float*)d_in[0];
    const float* vdirs  = (const float*)d_in[1];
    const float* planes = (const float*)d_in[4];
    const float* lines  = (const float*)d_in[5];
    const float* aabb   = (const float*)d_in[6];
    float* out = (float*)d_out;

    const int npts = in_sizes[0] / 3;

    voxelize<<<dim3(GRES / 4, GRES / 4), 128>>>(planes, lines);
    sample_warp<<<(npts + 255) / 256, 256>>>(xyz, vdirs, aabb, out, npts);
}

// round 7
// speedup vs baseline: 2.9423x; 1.2877x over previous
#include <cuda_runtime.h>
#include <cuda_fp16.h>
#include <math.h>

#define GRES 128
#define NPIX 16384

// Fused trilinear table: T[a2][a1][a0] -> uint4 (6 halves + pad). 33.5 MB.
__device__ uint4 g_T[GRES * GRES * GRES];

// Packed f32x2 helpers (sm_103a)
#define FMA2(d, a, b, c) \
    asm("fma.rn.f32x2 %0, %1, %2, %3;" : "=l"(d) : "l"(a), "l"(b), "l"(c))
#define PACK2(out, lo, hi) \
    asm("mov.b64 %0, {%1, %2};" : "=l"(out) : "f"(lo), "f"(hi))
#define UNPACK2(lo, hi, in) \
    asm("mov.b64 {%0, %1}, %2;" : "=f"(lo), "=f"(hi) : "l"(in))

// ---------------------------------------------------------------------------
// Voxelize, register-direct, s-split across grid.z (2 s-slices per block):
//   T[a2][a1][a0][s] = sum_c plane0[sc][a1][a0]*line0[sc][a2]
//                    + plane1[sc][a2][a0]*line1[sc][a1]
//                    + plane2[sc][a2][a1]*line2[sc][a0]
// Block = 128 thr = 4 warps (one a1 each) x 4-wide a2 quad, grid.z = s-group.
// Thread: 4 a0 x 4 a2 x 2 s = 16 f32x2 accumulators (static idx, ~32 regs).
// All 12 LDG.128 of a c-iter issued before any FMA (MLP=12). No barriers in
// the c-loop; tiny scalar tables staged once in smem.
// ---------------------------------------------------------------------------
__global__ __launch_bounds__(128)
void voxelize(const float* __restrict__ planes, const float* __restrict__ lines) {
    __shared__ float s_l0[2][16][4];       // line0[sl][c][a2 quad]
    __shared__ float s_l1[2][16][4];       // line1[sl][c][a1 quad]
    __shared__ float s_p2[2][16][4][4];    // plane2[sl][c][a1 local][a2 quad]

    const int tid  = threadIdx.x;
    const int lane = tid & 31;
    const int wid  = tid >> 5;             // local a1
    const int a1b  = blockIdx.x * 4;
    const int a2b  = blockIdx.y * 4;
    const int sg   = blockIdx.z;           // s-group: handles s = 2sg, 2sg+1
    const int a1   = a1b + wid;
    const int a0   = lane * 4;

    // ---- one-time staging of scalar tables ----
    for (int i = tid; i < 128; i += 128) {
        int sl = i >> 6, c = (i >> 2) & 15, d = i & 3;
        int sc = (2 * sg + sl) * 16 + c;
        s_l0[sl][c][d] = lines[(size_t)sc * GRES + a2b + d];
        s_l1[sl][c][d] = lines[(size_t)(96 + sc) * GRES + a1b + d];
    }
    for (int i = tid; i < 512; i += 128) {
        int sl = i >> 8, c = (i >> 4) & 15, r = (i >> 2) & 3, d = i & 3;
        int sc = (2 * sg + sl) * 16 + c;
        s_p2[sl][c][r][d] = planes[(size_t)(192 + sc) * NPIX + (a2b + d) * GRES + (a1b + r)];
    }
    __syncthreads();

    unsigned long long acc[2][4][2];
    #pragma unroll
    for (int sl = 0; sl < 2; sl++)
        #pragma unroll
        for (int d = 0; d < 4; d++) {
            acc[sl][d][0] = 0ull; acc[sl][d][1] = 0ull;
        }

    const float* __restrict__ p0base = planes;
    const float* __restrict__ p1base = planes + (size_t)96 * NPIX;
    const float* __restrict__ l2base = lines + (size_t)192 * GRES;

    for (int c = 0; c < 16; c++) {
        // ---- load phase: 12 independent LDG.128 ----
        ulonglong2 P0[2], L2[2], P1[2][4];
        #pragma unroll
        for (int sl = 0; sl < 2; sl++) {
            const int sc = (2 * sg + sl) * 16 + c;
            P0[sl] = __ldg((const ulonglong2*)(p0base + (size_t)sc * NPIX + a1 * GRES + a0));
            L2[sl] = __ldg((const ulonglong2*)(l2base + (size_t)sc * GRES + a0));
            #pragma unroll
            for (int d = 0; d < 4; d++)
                P1[sl][d] = __ldg((const ulonglong2*)(p1base + (size_t)sc * NPIX + (a2b + d) * GRES + a0));
        }

        // ---- compute phase ----
        #pragma unroll
        for (int sl = 0; sl < 2; sl++) {
            float4 l0q = *(const float4*)&s_l0[sl][c][0];       // warp-uniform
            float4 p2q = *(const float4*)&s_p2[sl][c][wid][0];  // warp-uniform
            float  l1s = s_l1[sl][c][wid];                      // warp-uniform
            unsigned long long l1d; PACK2(l1d, l1s, l1s);
            const float l0a[4] = {l0q.x, l0q.y, l0q.z, l0q.w};
            const float p2a[4] = {p2q.x, p2q.y, p2q.z, p2q.w};

            #pragma unroll
            for (int d = 0; d < 4; d++) {
                unsigned long long l0d, p2d;
                PACK2(l0d, l0a[d], l0a[d]);
                PACK2(p2d, p2a[d], p2a[d]);
                FMA2(acc[sl][d][0], P0[sl].x,    l0d, acc[sl][d][0]);
                FMA2(acc[sl][d][1], P0[sl].y,    l0d, acc[sl][d][1]);
                FMA2(acc[sl][d][0], P1[sl][d].x, l1d, acc[sl][d][0]);
                FMA2(acc[sl][d][1], P1[sl][d].y, l1d, acc[sl][d][1]);
                FMA2(acc[sl][d][0], L2[sl].x,    p2d, acc[sl][d][0]);
                FMA2(acc[sl][d][1], L2[sl].y,    p2d, acc[sl][d][1]);
            }
        }
    }

    // ---- epilogue: this s-group writes its half2 (4B) of each uint4 record ----
    #pragma unroll
    for (int d = 0; d < 4; d++) {
        float v0[4], v1[4];                 // v[s-local][a0 offset j]
        UNPACK2(v0[0], v0[1], acc[0][d][0]);
        UNPACK2(v0[2], v0[3], acc[0][d][1]);
        UNPACK2(v1[0], v1[1], acc[1][d][0]);
        UNPACK2(v1[2], v1[3], acc[1][d][1]);
        unsigned* base = reinterpret_cast<unsigned*>(g_T)
                       + ((((size_t)(a2b + d)) * GRES + a1) * GRES + a0) * 4 + sg;
        #pragma unroll
        for (int j = 0; j < 4; j++) {
            __half2 h = __floats2half2_rn(v0[j], v1[j]);
            base[j * 4] = *reinterpret_cast<unsigned*>(&h);
        }
    }
}

// ---------------------------------------------------------------------------
// Sample + Rodrigues: one thread per point; 8 LDG.128 trilinear gathers.
// ---------------------------------------------------------------------------
__device__ __forceinline__ void unp6(uint4 q, float f[6]) {
    __half2 h0 = *reinterpret_cast<__half2*>(&q.x);
    __half2 h1 = *reinterpret_cast<__half2*>(&q.y);
    __half2 h2 = *reinterpret_cast<__half2*>(&q.z);
    float2 a = __half22float2(h0);
    float2 b = __half22float2(h1);
    float2 c = __half22float2(h2);
    f[0] = a.x; f[1] = a.y; f[2] = b.x; f[3] = b.y; f[4] = c.x; f[5] = c.y;
}

__global__ __launch_bounds__(256)
void sample_warp(const float* __restrict__ xyz, const float* __restrict__ vd,
                 const float* __restrict__ aabb, float* __restrict__ out,
                 int npts) {
    int pt = blockIdx.x * 256 + threadIdx.x;
    if (pt >= npts) return;

    const float X0 = xyz[pt * 3 + 0], X1 = xyz[pt * 3 + 1], X2 = xyz[pt * 3 + 2];
    const float Pc[3] = {X0, X1, X2};

    int ii[2][3];
    float w[3];
    #pragma unroll
    for (int d = 0; d < 3; d++) {
        float lo = __ldg(&aabb[d]), hi = __ldg(&aabb[3 + d]);
        float xn = (Pc[d] - lo) * (2.0f / (hi - lo)) - 1.0f;
        float f = fmaf(xn, 63.5f, 63.5f);
        f = fminf(fmaxf(f, 0.0f), 127.0f);
        float ff = floorf(f);
        ii[0][d] = (int)ff;
        ii[1][d] = min(ii[0][d] + 1, GRES - 1);
        w[d] = f - ff;
    }

    float f[2][2][2][6];
    #pragma unroll
    for (int c2 = 0; c2 < 2; c2++)
        #pragma unroll
        for (int c1 = 0; c1 < 2; c1++)
            #pragma unroll
            for (int c0 = 0; c0 < 2; c0++) {
                uint4 q = __ldg(&g_T[((size_t)ii[c2][2] * GRES + ii[c1][1]) * GRES
                                     + ii[c0][0]]);
                unp6(q, f[c2][c1][c0]);
            }

    float bw[6];
    #pragma unroll
    for (int j = 0; j < 6; j++) {
        float e00 = fmaf(w[0], f[0][0][1][j] - f[0][0][0][j], f[0][0][0][j]);
        float e01 = fmaf(w[0], f[0][1][1][j] - f[0][1][0][j], f[0][1][0][j]);
        float e10 = fmaf(w[0], f[1][0][1][j] - f[1][0][0][j], f[1][0][0][j]);
        float e11 = fmaf(w[0], f[1][1][1][j] - f[1][1][0][j], f[1][1][0][j]);
        float g0  = fmaf(w[1], e01 - e00, e00);
        float g1  = fmaf(w[1], e11 - e10, e10);
        bw[j] = fmaf(w[2], g1 - g0, g0);
    }

    float w0 = bw[0], w1 = bw[1], w2 = bw[2];
    float v0 = bw[3], v1 = bw[4], v2 = bw[5];

    float th2 = fmaf(w0, w0, fmaf(w1, w1, w2 * w2));
    th2 = fmaxf(th2, 1e-6f);
    float th  = sqrtf(th2);
    float inv = 1.0f / th;
    w0 *= inv; w1 *= inv; w2 *= inv;
    v0 *= inv; v1 *= inv; v2 *= inv;

    float q  = fmaf(w0, w0, fmaf(w1, w1, w2 * w2));
    float s  = sinf(th);
    float co = cosf(th);
    float cm = 1.0f - co;
    float ts = th - s;

    float rD = 1.0f - cm * q;
    float pD = th - ts * q;

    float D0 = vd[pt * 3 + 0], D1 = vd[pt * 3 + 1], D2 = vd[pt * 3 + 2];

    float wdV = fmaf(w0, v0, fmaf(w1, v1, w2 * v2));
    float t0 = pD * v0 + cm * (w1 * v2 - w2 * v1) + ts * w0 * wdV;
    float t1 = pD * v1 + cm * (w2 * v0 - w0 * v2) + ts * w1 * wdV;
    float t2 = pD * v2 + cm * (w0 * v1 - w1 * v0) + ts * w2 * wdV;

    float wdX = fmaf(w0, X0, fmaf(w1, X1, w2 * X2));
    float xw0 = rD * X0 + s * (w1 * X2 - w2 * X1) + cm * w0 * wdX + t0;
    float xw1 = rD * X1 + s * (w2 * X0 - w0 * X2) + cm * w1 * wdX + t1;
    float xw2 = rD * X2 + s * (w0 * X1 - w1 * X0) + cm * w2 * wdX + t2;

    float wdD = fmaf(w0, D0, fmaf(w1, D1, w2 * D2));
    float vw0 = rD * D0 + s * (w1 * D2 - w2 * D1) + cm * w0 * wdD;
    float vw1 = rD * D1 + s * (w2 * D0 - w0 * D2) + cm * w1 * wdD;
    float vw2 = rD * D2 + s * (w0 * D1 - w1 * D0) + cm * w2 * wdD;

    out[(size_t)pt * 3 + 0] = xw0;
    out[(size_t)pt * 3 + 1] = xw1;
    out[(size_t)pt * 3 + 2] = xw2;
    size_t off = (size_t)npts * 3;
    out[off + (size_t)pt * 3 + 0] = vw0;
    out[off + (size_t)pt * 3 + 1] = vw1;
    out[off + (size_t)pt * 3 + 2] = vw2;
}

// ---------------------------------------------------------------------------
extern "C" void kernel_launch(void* const* d_in, const int* in_sizes, int n_in,
                              void* d_out, int out_size) {
    const float* xyz    = (const float*)d_in[0];
    const float* vdirs  = (const float*)d_in[1];
    const float* planes = (const float*)d_in[4];
    const float* lines  = (const float*)d_in[5];
    const float* aabb   = (const float*)d_in[6];
    float* out = (float*)d_out;

    const int npts = in_sizes[0] / 3;

    voxelize<<<dim3(GRES / 4, GRES / 4, 3), 128>>>(planes, lines);
    sample_warp<<<(npts + 255) / 256, 256>>>(xyz, vdirs, aabb, out, npts);
}

// round 8
// speedup vs baseline: 3.0194x; 1.0262x over previous
#include <cuda_runtime.h>
#include <cuda_fp16.h>
#include <math.h>

#define GRES 128
#define NPIX 16384

// Fused trilinear table: T[a2][a1][a0] -> uint4 (6 halves + pad). 33.5 MB.
__device__ uint4 g_T[GRES * GRES * GRES];
// fp16 copies of plane groups p0,p1 (same layout: [sc][a1|a2][a0]). 6.3 MB.
__device__ __half g_p01H[2 * 96 * NPIX];

// Packed f32x2 helpers (sm_103a)
#define FMA2(d, a, b, c) \
    asm("fma.rn.f32x2 %0, %1, %2, %3;" : "=l"(d) : "l"(a), "l"(b), "l"(c))
#define PACK2(out, lo, hi) \
    asm("mov.b64 %0, {%1, %2};" : "=l"(out) : "f"(lo), "f"(hi))
#define UNPACK2(lo, hi, in) \
    asm("mov.b64 {%0, %1}, %2;" : "=f"(lo), "=f"(hi) : "l"(in))

// ---------------------------------------------------------------------------
// Convert planes[0:192] (p0,p1 groups) fp32 -> fp16, same linear layout.
// ---------------------------------------------------------------------------
__global__ void prep_h(const float* __restrict__ planes) {
    int i = blockIdx.x * 256 + threadIdx.x;          // over 786432 float4s
    if (i >= 2 * 96 * NPIX / 4) return;
    float4 v = __ldg((const float4*)planes + i);
    __half2 h0 = __floats2half2_rn(v.x, v.y);
    __half2 h1 = __floats2half2_rn(v.z, v.w);
    uint2 q;
    q.x = *reinterpret_cast<unsigned*>(&h0);
    q.y = *reinterpret_cast<unsigned*>(&h1);
    reinterpret_cast<uint2*>(g_p01H)[i] = q;
}

// Load 4 halves -> two packed f32x2
__device__ __forceinline__ void ld4h(const uint2* __restrict__ p,
                                     unsigned long long& lo,
                                     unsigned long long& hi) {
    uint2 q = __ldg(p);
    float2 a = __half22float2(*reinterpret_cast<__half2*>(&q.x));
    float2 b = __half22float2(*reinterpret_cast<__half2*>(&q.y));
    PACK2(lo, a.x, a.y);
    PACK2(hi, b.x, b.y);
}

// ---------------------------------------------------------------------------
// Voxelize, register-direct, s-split (grid.z=3, 2 s-slices per block):
//   T[a2][a1][a0][s] = sum_c plane0[sc][a1][a0]*line0[sc][a2]
//                    + plane1[sc][a2][a0]*line1[sc][a1]
//                    + plane2[sc][a2][a1]*line2[sc][a0]
// P0/P1 streamed as fp16 LDG.64 (halves L1 wavefronts + L2 bytes); line2
// rows stay fp32 (L1-resident). fp32 accumulation in 16 f32x2 registers.
// Block = 128 thr = 4 warps (one a1 each) x 4-wide a2 quad.
// ---------------------------------------------------------------------------
__global__ __launch_bounds__(128)
void voxelize(const float* __restrict__ planes, const float* __restrict__ lines) {
    __shared__ float s_l0[2][16][4];       // line0[sl][c][a2 quad]
    __shared__ float s_l1[2][16][4];       // line1[sl][c][a1 quad]
    __shared__ float s_p2[2][16][4][4];    // plane2[sl][c][a1 local][a2 quad]

    const int tid  = threadIdx.x;
    const int lane = tid & 31;
    const int wid  = tid >> 5;             // local a1
    const int a1b  = blockIdx.x * 4;
    const int a2b  = blockIdx.y * 4;
    const int sg   = blockIdx.z;           // s-group: s = 2sg, 2sg+1
    const int a1   = a1b + wid;
    const int a0   = lane * 4;

    // ---- one-time staging of scalar tables (fp32, exact) ----
    for (int i = tid; i < 128; i += 128) {
        int sl = i >> 6, c = (i >> 2) & 15, d = i & 3;
        int sc = (2 * sg + sl) * 16 + c;
        s_l0[sl][c][d] = lines[(size_t)sc * GRES + a2b + d];
        s_l1[sl][c][d] = lines[(size_t)(96 + sc) * GRES + a1b + d];
    }
    for (int i = tid; i < 512; i += 128) {
        int sl = i >> 8, c = (i >> 4) & 15, r = (i >> 2) & 3, d = i & 3;
        int sc = (2 * sg + sl) * 16 + c;
        s_p2[sl][c][r][d] = planes[(size_t)(192 + sc) * NPIX + (a2b + d) * GRES + (a1b + r)];
    }
    __syncthreads();

    unsigned long long acc[2][4][2];
    #pragma unroll
    for (int sl = 0; sl < 2; sl++)
        #pragma unroll
        for (int d = 0; d < 4; d++) {
            acc[sl][d][0] = 0ull; acc[sl][d][1] = 0ull;
        }

    const __half* __restrict__ p0base = g_p01H;
    const __half* __restrict__ p1base = g_p01H + (size_t)96 * NPIX;
    const float*  __restrict__ l2base = lines + (size_t)192 * GRES;

    for (int c = 0; c < 16; c++) {
        // ---- load phase: 12 independent loads (10 fp16 LDG.64 + 2 LDG.128) ----
        unsigned long long P0[2][2], L2[2], P1[2][4][2];
        #pragma unroll
        for (int sl = 0; sl < 2; sl++) {
            const int sc = (2 * sg + sl) * 16 + c;
            ld4h((const uint2*)(p0base + (size_t)sc * NPIX + a1 * GRES + a0),
                 P0[sl][0], P0[sl][1]);
            ulonglong2 l2v = __ldg((const ulonglong2*)(l2base + (size_t)sc * GRES + a0));
            L2[sl] = l2v.x;                // reuse as two u64 (f32 pairs)
            acc[sl][0][0] = acc[sl][0][0]; // no-op, keep structure
            unsigned long long l2hi = l2v.y;
            #pragma unroll
            for (int d = 0; d < 4; d++)
                ld4h((const uint2*)(p1base + (size_t)sc * NPIX + (a2b + d) * GRES + a0),
                     P1[sl][d][0], P1[sl][d][1]);

            // ---- compute for this sl (keeps l2hi live locally) ----
            float4 l0q = *(const float4*)&s_l0[sl][c][0];       // warp-uniform
            float4 p2q = *(const float4*)&s_p2[sl][c][wid][0];  // warp-uniform
            float  l1s = s_l1[sl][c][wid];                      // warp-uniform
            unsigned long long l1d; PACK2(l1d, l1s, l1s);
            const float l0a[4] = {l0q.x, l0q.y, l0q.z, l0q.w};
            const float p2a[4] = {p2q.x, p2q.y, p2q.z, p2q.w};

            #pragma unroll
            for (int d = 0; d < 4; d++) {
                unsigned long long l0d, p2d;
                PACK2(l0d, l0a[d], l0a[d]);
                PACK2(p2d, p2a[d], p2a[d]);
                FMA2(acc[sl][d][0], P0[sl][0],    l0d, acc[sl][d][0]);
                FMA2(acc[sl][d][1], P0[sl][1],    l0d, acc[sl][d][1]);
                FMA2(acc[sl][d][0], P1[sl][d][0], l1d, acc[sl][d][0]);
                FMA2(acc[sl][d][1], P1[sl][d][1], l1d, acc[sl][d][1]);
                FMA2(acc[sl][d][0], L2[sl],       p2d, acc[sl][d][0]);
                FMA2(acc[sl][d][1], l2hi,         p2d, acc[sl][d][1]);
            }
        }
    }

    // ---- epilogue: this s-group writes its half2 (4B) of each uint4 record ----
    #pragma unroll
    for (int d = 0; d < 4; d++) {
        float v0[4], v1[4];
        UNPACK2(v0[0], v0[1], acc[0][d][0]);
        UNPACK2(v0[2], v0[3], acc[0][d][1]);
        UNPACK2(v1[0], v1[1], acc[1][d][0]);
        UNPACK2(v1[2], v1[3], acc[1][d][1]);
        unsigned* base = reinterpret_cast<unsigned*>(g_T)
                       + ((((size_t)(a2b + d)) * GRES + a1) * GRES + a0) * 4 + sg;
        #pragma unroll
        for (int j = 0; j < 4; j++) {
            __half2 h = __floats2half2_rn(v0[j], v1[j]);
            base[j * 4] = *reinterpret_cast<unsigned*>(&h);
        }
    }
}

// ---------------------------------------------------------------------------
// Sample + Rodrigues: one thread per point; 8 LDG.128 trilinear gathers.
// ---------------------------------------------------------------------------
__device__ __forceinline__ void unp6(uint4 q, float f[6]) {
    __half2 h0 = *reinterpret_cast<__half2*>(&q.x);
    __half2 h1 = *reinterpret_cast<__half2*>(&q.y);
    __half2 h2 = *reinterpret_cast<__half2*>(&q.z);
    float2 a = __half22float2(h0);
    float2 b = __half22float2(h1);
    float2 c = __half22float2(h2);
    f[0] = a.x; f[1] = a.y; f[2] = b.x; f[3] = b.y; f[4] = c.x; f[5] = c.y;
}

__global__ __launch_bounds__(256)
void sample_warp(const float* __restrict__ xyz, const float* __restrict__ vd,
                 const float* __restrict__ aabb, float* __restrict__ out,
                 int npts) {
    int pt = blockIdx.x * 256 + threadIdx.x;
    if (pt >= npts) return;

    const float X0 = xyz[pt * 3 + 0], X1 = xyz[pt * 3 + 1], X2 = xyz[pt * 3 + 2];
    const float Pc[3] = {X0, X1, X2};

    int ii[2][3];
    float w[3];
    #pragma unroll
    for (int d = 0; d < 3; d++) {
        float lo = __ldg(&aabb[d]), hi = __ldg(&aabb[3 + d]);
        float xn = (Pc[d] - lo) * (2.0f / (hi - lo)) - 1.0f;
        float f = fmaf(xn, 63.5f, 63.5f);
        f = fminf(fmaxf(f, 0.0f), 127.0f);
        float ff = floorf(f);
        ii[0][d] = (int)ff;
        ii[1][d] = min(ii[0][d] + 1, GRES - 1);
        w[d] = f - ff;
    }

    float f[2][2][2][6];
    #pragma unroll
    for (int c2 = 0; c2 < 2; c2++)
        #pragma unroll
        for (int c1 = 0; c1 < 2; c1++)
            #pragma unroll
            for (int c0 = 0; c0 < 2; c0++) {
                uint4 q = __ldg(&g_T[((size_t)ii[c2][2] * GRES + ii[c1][1]) * GRES
                                     + ii[c0][0]]);
                unp6(q, f[c2][c1][c0]);
            }

    float bw[6];
    #pragma unroll
    for (int j = 0; j < 6; j++) {
        float e00 = fmaf(w[0], f[0][0][1][j] - f[0][0][0][j], f[0][0][0][j]);
        float e01 = fmaf(w[0], f[0][1][1][j] - f[0][1][0][j], f[0][1][0][j]);
        float e10 = fmaf(w[0], f[1][0][1][j] - f[1][0][0][j], f[1][0][0][j]);
        float e11 = fmaf(w[0], f[1][1][1][j] - f[1][1][0][j], f[1][1][0][j]);
        float g0  = fmaf(w[1], e01 - e00, e00);
        float g1  = fmaf(w[1], e11 - e10, e10);
        bw[j] = fmaf(w[2], g1 - g0, g0);
    }

    float w0 = bw[0], w1 = bw[1], w2 = bw[2];
    float v0 = bw[3], v1 = bw[4], v2 = bw[5];

    float th2 = fmaf(w0, w0, fmaf(w1, w1, w2 * w2));
    th2 = fmaxf(th2, 1e-6f);
    float th  = sqrtf(th2);
    float inv = 1.0f / th;
    w0 *= inv; w1 *= inv; w2 *= inv;
    v0 *= inv; v1 *= inv; v2 *= inv;

    float q  = fmaf(w0, w0, fmaf(w1, w1, w2 * w2));
    float s  = sinf(th);
    float co = cosf(th);
    float cm = 1.0f - co;
    float ts = th - s;

    float rD = 1.0f - cm * q;
    float pD = th - ts * q;

    float D0 = vd[pt * 3 + 0], D1 = vd[pt * 3 + 1], D2 = vd[pt * 3 + 2];

    float wdV = fmaf(w0, v0, fmaf(w1, v1, w2 * v2));
    float t0 = pD * v0 + cm * (w1 * v2 - w2 * v1) + ts * w0 * wdV;
    float t1 = pD * v1 + cm * (w2 * v0 - w0 * v2) + ts * w1 * wdV;
    float t2 = pD * v2 + cm * (w0 * v1 - w1 * v0) + ts * w2 * wdV;

    float wdX = fmaf(w0, X0, fmaf(w1, X1, w2 * X2));
    float xw0 = rD * X0 + s * (w1 * X2 - w2 * X1) + cm * w0 * wdX + t0;
    float xw1 = rD * X1 + s * (w2 * X0 - w0 * X2) + cm * w1 * wdX + t1;
    float xw2 = rD * X2 + s * (w0 * X1 - w1 * X0) + cm * w2 * wdX + t2;

    float wdD = fmaf(w0, D0, fmaf(w1, D1, w2 * D2));
    float vw0 = rD * D0 + s * (w1 * D2 - w2 * D1) + cm * w0 * wdD;
    float vw1 = rD * D1 + s * (w2 * D0 - w0 * D2) + cm * w1 * wdD;
    float vw2 = rD * D2 + s * (w0 * D1 - w1 * D0) + cm * w2 * wdD;

    out[(size_t)pt * 3 + 0] = xw0;
    out[(size_t)pt * 3 + 1] = xw1;
    out[(size_t)pt * 3 + 2] = xw2;
    size_t off = (size_t)npts * 3;
    out[off + (size_t)pt * 3 + 0] = vw0;
    out[off + (size_t)pt * 3 + 1] = vw1;
    out[off + (size_t)pt * 3 + 2] = vw2;
}

// ---------------------------------------------------------------------------
extern "C" void kernel_launch(void* const* d_in, const int* in_sizes, int n_in,
                              void* d_out, int out_size) {
    const float* xyz    = (const float*)d_in[0];
    const float* vdirs  = (const float*)d_in[1];
    const float* planes = (const float*)d_in[4];
    const float* lines  = (const float*)d_in[5];
    const float* aabb   = (const float*)d_in[6];
    float* out = (float*)d_out;

    const int npts = in_sizes[0] / 3;

    prep_h<<<(2 * 96 * NPIX / 4 + 255) / 256, 256>>>(planes);
    voxelize<<<dim3(GRES / 4, GRES / 4, 3), 128>>>(planes, lines);
    sample_warp<<<(npts + 255) / 256, 256>>>(xyz, vdirs, aabb, out, npts);
}

// round 9
// speedup vs baseline: 4.1116x; 1.3617x over previous
#include <cuda_runtime.h>
#include <cuda_fp16.h>
#include <math.h>

#define GRES 128
#define NPIX 16384

// Fused trilinear table: T[a2][a1][a0] -> uint4 (6 halves + pad). 33.5 MB.
__device__ uint4 g_T[GRES * GRES * GRES];
// s-interleaved fp16 plane streams: [g(2)][sg(3)][c(16)][px] = half2(s0,s1). 6.3 MB
__device__ unsigned g_pH[2 * 3 * 16 * NPIX];
// s-interleaved fp16 line2 rows: [sg][c][a0] = half2(s0,s1). 24 KB
__device__ unsigned g_L2H[3 * 16 * GRES];

__device__ __forceinline__ __half2 u2h(unsigned u) {
    return *reinterpret_cast<__half2*>(&u);
}
__device__ __forceinline__ unsigned h2u(__half2 h) {
    return *reinterpret_cast<unsigned*>(&h);
}

// ---------------------------------------------------------------------------
// Prep: build s-interleaved fp16 streams for plane groups 0,1.
// out[((g*3+sg)*16+c)][px] = half2(P[g*96 + 2sg*16+c][px], P[g*96+(2sg+1)*16+c][px])
// ---------------------------------------------------------------------------
__global__ void prep_ph(const float* __restrict__ planes) {
    int o = blockIdx.x * 256 + threadIdx.x;          // over 786432 pixel-pairs
    if (o >= 2 * 3 * 16 * (NPIX / 2)) return;
    int pp = o & 8191;
    int t  = o >> 13;
    int c  = t & 15;  t >>= 4;
    int sg = t % 3;
    int g  = t / 3;
    const float2* s0 = (const float2*)(planes + ((size_t)(g * 96 + (2 * sg) * 16 + c) << 14)) + pp;
    const float2* s1 = (const float2*)(planes + ((size_t)(g * 96 + (2 * sg + 1) * 16 + c) << 14)) + pp;
    float2 v0 = __ldg(s0);
    float2 v1 = __ldg(s1);
    uint2 q;
    q.x = h2u(__floats2half2_rn(v0.x, v1.x));
    q.y = h2u(__floats2half2_rn(v0.y, v1.y));
    reinterpret_cast<uint2*>(g_pH)[((g * 3 + sg) * 16 + c) * 8192 + pp] = q;
}

// Prep: s-interleaved fp16 line2 rows.
__global__ void prep_lh(const float* __restrict__ lines) {
    int o = blockIdx.x * 256 + threadIdx.x;          // over 6144
    if (o >= 3 * 16 * GRES) return;
    int x = o & 127;
    int c = (o >> 7) & 15;
    int sg = o >> 11;
    float v0 = __ldg(&lines[(size_t)(192 + (2 * sg) * 16 + c) * GRES + x]);
    float v1 = __ldg(&lines[(size_t)(192 + (2 * sg + 1) * 16 + c) * GRES + x]);
    g_L2H[o] = h2u(__floats2half2_rn(v0, v1));
}

// ---------------------------------------------------------------------------
// Voxelize, all-fp16 HFMA2, s-interleaved (grid.z = sg handles s = 2sg, 2sg+1):
//   T[a2][a1][a0][s] = sum_c plane0[sc][a1][a0]*line0[sc][a2]
//                    + plane1[sc][a2][a0]*line1[sc][a1]
//                    + plane2[sc][a2][a1]*line2[sc][a0]
// Accumulators ARE the output half2(s0,s1) -> no converts anywhere in the
// main loop (6 LDG.128 + 48 HFMA2 + 3 LDS per c-iter). ~50 regs -> high occ.
// Block = 128 thr = 4 warps (one a1 each) x 4-wide a2 quad.
// ---------------------------------------------------------------------------
__global__ __launch_bounds__(128)
void voxelize(const float* __restrict__ planes, const float* __restrict__ lines) {
    __shared__ __align__(16) __half2 s_l0[16][4];      // [c][d]   line0 splat
    __shared__ __align__(16) __half2 s_l1[16][4];      // [c][wid] line1 splat
    __shared__ __align__(16) __half2 s_p2[16][4][4];   // [c][wid][d] plane2 splat

    const int tid  = threadIdx.x;
    const int lane = tid & 31;
    const int wid  = tid >> 5;             // local a1
    const int a1b  = blockIdx.x * 4;
    const int a2b  = blockIdx.y * 4;
    const int sg   = blockIdx.z;           // s-group: s = 2sg, 2sg+1
    const int a1   = a1b + wid;
    const int a0   = lane * 4;

    // ---- one-time staging of scalar splats (fp32 inputs -> half2 pairs) ----
    {
        int i = tid;                                   // 128 entries: l0 | l1
        int c = (i >> 2) & 15, d = i & 3;
        int sc0 = (2 * sg) * 16 + c, sc1 = sc0 + 16;
        if (i < 64) {
            float v0 = lines[(size_t)sc0 * GRES + a2b + d];
            float v1 = lines[(size_t)sc1 * GRES + a2b + d];
            s_l0[c][d] = __floats2half2_rn(v0, v1);
        } else {
            float v0 = lines[(size_t)(96 + sc0) * GRES + a1b + d];
            float v1 = lines[(size_t)(96 + sc1) * GRES + a1b + d];
            s_l1[c][d] = __floats2half2_rn(v0, v1);
        }
    }
    for (int i = tid; i < 256; i += 128) {             // p2: [c][w][d]
        int c = i >> 4, w = (i >> 2) & 3, d = i & 3;
        int sc0 = (2 * sg) * 16 + c, sc1 = sc0 + 16;
        float v0 = planes[(size_t)(192 + sc0) * NPIX + (a2b + d) * GRES + (a1b + w)];
        float v1 = planes[(size_t)(192 + sc1) * NPIX + (a2b + d) * GRES + (a1b + w)];
        s_p2[c][w][d] = __floats2half2_rn(v0, v1);
    }
    __syncthreads();

    __half2 acc[4][4];                     // [d = a2 local][j = a0 offset]
    #pragma unroll
    for (int d = 0; d < 4; d++)
        #pragma unroll
        for (int j = 0; j < 4; j++)
            acc[d][j] = __floats2half2_rn(0.0f, 0.0f);

    const unsigned* __restrict__ P0b = g_pH + (((size_t)sg * 16) << 14);
    const unsigned* __restrict__ P1b = g_pH + (((size_t)(48 + sg * 16)) << 14);
    const unsigned* __restrict__ L2b = g_L2H + sg * 16 * GRES;

    for (int c = 0; c < 16; c++) {
        uint4 P0 = __ldg((const uint4*)(P0b + ((size_t)c << 14) + a1 * GRES + a0));
        uint4 L2 = __ldg((const uint4*)(L2b + c * GRES + a0));
        const __half2 p0j[4] = {u2h(P0.x), u2h(P0.y), u2h(P0.z), u2h(P0.w)};
        const __half2 l2j[4] = {u2h(L2.x), u2h(L2.y), u2h(L2.z), u2h(L2.w)};

        uint4 l0u = *(const uint4*)&s_l0[c][0];        // warp-uniform
        uint4 p2u = *(const uint4*)&s_p2[c][wid][0];   // warp-uniform
        const __half2 l1w = s_l1[c][wid];              // warp-uniform
        const __half2 l0d[4] = {u2h(l0u.x), u2h(l0u.y), u2h(l0u.z), u2h(l0u.w)};
        const __half2 p2d[4] = {u2h(p2u.x), u2h(p2u.y), u2h(p2u.z), u2h(p2u.w)};

        #pragma unroll
        for (int d = 0; d < 4; d++) {
            uint4 P1 = __ldg((const uint4*)(P1b + ((size_t)c << 14) + (a2b + d) * GRES + a0));
            const __half2 p1j[4] = {u2h(P1.x), u2h(P1.y), u2h(P1.z), u2h(P1.w)};
            #pragma unroll
            for (int j = 0; j < 4; j++) {
                acc[d][j] = __hfma2(p0j[j], l0d[d], acc[d][j]);
                acc[d][j] = __hfma2(p1j[j], l1w,    acc[d][j]);
                acc[d][j] = __hfma2(l2j[j], p2d[d], acc[d][j]);
            }
        }
    }

    // ---- epilogue: accumulators ARE the stored half2 (offset sg in uint4) ----
    #pragma unroll
    for (int d = 0; d < 4; d++) {
        unsigned* base = reinterpret_cast<unsigned*>(g_T)
                       + ((((size_t)(a2b + d)) * GRES + a1) * GRES + a0) * 4 + sg;
        #pragma unroll
        for (int j = 0; j < 4; j++)
            base[j * 4] = h2u(acc[d][j]);
    }
}

// ---------------------------------------------------------------------------
// Sample + Rodrigues: one thread per point; 8 LDG.128 trilinear gathers.
// ---------------------------------------------------------------------------
__device__ __forceinline__ void unp6(uint4 q, float f[6]) {
    float2 a = __half22float2(u2h(q.x));
    float2 b = __half22float2(u2h(q.y));
    float2 c = __half22float2(u2h(q.z));
    f[0] = a.x; f[1] = a.y; f[2] = b.x; f[3] = b.y; f[4] = c.x; f[5] = c.y;
}

__global__ __launch_bounds__(256)
void sample_warp(const float* __restrict__ xyz, const float* __restrict__ vd,
                 const float* __restrict__ aabb, float* __restrict__ out,
                 int npts) {
    int pt = blockIdx.x * 256 + threadIdx.x;
    if (pt >= npts) return;

    const float X0 = xyz[pt * 3 + 0], X1 = xyz[pt * 3 + 1], X2 = xyz[pt * 3 + 2];
    const float Pc[3] = {X0, X1, X2};

    int ii[2][3];
    float w[3];
    #pragma unroll
    for (int d = 0; d < 3; d++) {
        float lo = __ldg(&aabb[d]), hi = __ldg(&aabb[3 + d]);
        float xn = (Pc[d] - lo) * (2.0f / (hi - lo)) - 1.0f;
        float f = fmaf(xn, 63.5f, 63.5f);
        f = fminf(fmaxf(f, 0.0f), 127.0f);
        float ff = floorf(f);
        ii[0][d] = (int)ff;
        ii[1][d] = min(ii[0][d] + 1, GRES - 1);
        w[d] = f - ff;
    }

    float f[2][2][2][6];
    #pragma unroll
    for (int c2 = 0; c2 < 2; c2++)
        #pragma unroll
        for (int c1 = 0; c1 < 2; c1++)
            #pragma unroll
            for (int c0 = 0; c0 < 2; c0++) {
                uint4 q = __ldg(&g_T[((size_t)ii[c2][2] * GRES + ii[c1][1]) * GRES
                                     + ii[c0][0]]);
                unp6(q, f[c2][c1][c0]);
            }

    float bw[6];
    #pragma unroll
    for (int j = 0; j < 6; j++) {
        float e00 = fmaf(w[0], f[0][0][1][j] - f[0][0][0][j], f[0][0][0][j]);
        float e01 = fmaf(w[0], f[0][1][1][j] - f[0][1][0][j], f[0][1][0][j]);
        float e10 = fmaf(w[0], f[1][0][1][j] - f[1][0][0][j], f[1][0][0][j]);
        float e11 = fmaf(w[0], f[1][1][1][j] - f[1][1][0][j], f[1][1][0][j]);
        float g0  = fmaf(w[1], e01 - e00, e00);
        float g1  = fmaf(w[1], e11 - e10, e10);
        bw[j] = fmaf(w[2], g1 - g0, g0);
    }

    float w0 = bw[0], w1 = bw[1], w2 = bw[2];
    float v0 = bw[3], v1 = bw[4], v2 = bw[5];

    float th2 = fmaf(w0, w0, fmaf(w1, w1, w2 * w2));
    th2 = fmaxf(th2, 1e-6f);
    float th  = sqrtf(th2);
    float inv = 1.0f / th;
    w0 *= inv; w1 *= inv; w2 *= inv;
    v0 *= inv; v1 *= inv; v2 *= inv;

    float q  = fmaf(w0, w0, fmaf(w1, w1, w2 * w2));
    float s  = sinf(th);
    float co = cosf(th);
    float cm = 1.0f - co;
    float ts = th - s;

    float rD = 1.0f - cm * q;
    float pD = th - ts * q;

    float D0 = vd[pt * 3 + 0], D1 = vd[pt * 3 + 1], D2 = vd[pt * 3 + 2];

    float wdV = fmaf(w0, v0, fmaf(w1, v1, w2 * v2));
    float t0 = pD * v0 + cm * (w1 * v2 - w2 * v1) + ts * w0 * wdV;
    float t1 = pD * v1 + cm * (w2 * v0 - w0 * v2) + ts * w1 * wdV;
    float t2 = pD * v2 + cm * (w0 * v1 - w1 * v0) + ts * w2 * wdV;

    float wdX = fmaf(w0, X0, fmaf(w1, X1, w2 * X2));
    float xw0 = rD * X0 + s * (w1 * X2 - w2 * X1) + cm * w0 * wdX + t0;
    float xw1 = rD * X1 + s * (w2 * X0 - w0 * X2) + cm * w1 * wdX + t1;
    float xw2 = rD * X2 + s * (w0 * X1 - w1 * X0) + cm * w2 * wdX + t2;

    float wdD = fmaf(w0, D0, fmaf(w1, D1, w2 * D2));
    float vw0 = rD * D0 + s * (w1 * D2 - w2 * D1) + cm * w0 * wdD;
    float vw1 = rD * D1 + s * (w2 * D0 - w0 * D2) + cm * w1 * wdD;
    float vw2 = rD * D2 + s * (w0 * D1 - w1 * D0) + cm * w2 * wdD;

    out[(size_t)pt * 3 + 0] = xw0;
    out[(size_t)pt * 3 + 1] = xw1;
    out[(size_t)pt * 3 + 2] = xw2;
    size_t off = (size_t)npts * 3;
    out[off + (size_t)pt * 3 + 0] = vw0;
    out[off + (size_t)pt * 3 + 1] = vw1;
    out[off + (size_t)pt * 3 + 2] = vw2;
}

// ---------------------------------------------------------------------------
extern "C" void kernel_launch(void* const* d_in, const int* in_sizes, int n_in,
                              void* d_out, int out_size) {
    const float* xyz    = (const float*)d_in[0];
    const float* vdirs  = (const float*)d_in[1];
    const float* planes = (const float*)d_in[4];
    const float* lines  = (const float*)d_in[5];
    const float* aabb   = (const float*)d_in[6];
    float* out = (float*)d_out;

    const int npts = in_sizes[0] / 3;

    prep_ph<<<(2 * 3 * 16 * (NPIX / 2) + 255) / 256, 256>>>(planes);
    prep_lh<<<(3 * 16 * GRES + 255) / 256, 256>>>(lines);
    voxelize<<<dim3(GRES / 4, GRES / 4, 3), 128>>>(planes, lines);
    sample_warp<<<(npts + 255) / 256, 256>>>(xyz, vdirs, aabb, out, npts);
}